// round 7
// baseline (speedup 1.0000x reference)
#include <cuda_runtime.h>
#include <math.h>

// Problem shapes (fixed by setup_inputs)
#define NB 2
#define NF 2
#define NX 256
#define NY 256
#define NZ 16
#define NR 24
#define NBF (NB*NF)
#define NOUT (NBF*NR*NZ)   // 1536

#define NBLK NX            // 256 blocks per bf (1 x-row each)

// SC = sqrt(50*log2(e)) * (pi/12)  (bin spacing in ex2-scaled units)
#define SC   2.2235193f

// Global accumulators (zero-init; last block per bf resets them each launch)
__device__ float g_sum[NOUT];
__device__ int   g_count[NBF];

__global__ __launch_bounds__(256, 7)
void gre_fused_kernel(const float* __restrict__ x,
                      const float* __restrict__ com_r,
                      const float* __restrict__ com_i,
                      float* __restrict__ out) {
    __shared__ float sm[27][256];   // row i = bin (i-1); bins -1..25
    __shared__ bool  s_last;

    const int bf  = blockIdx.y;     // 0..3
    const int xi  = blockIdx.x;     // x-row 0..255
    const int tid = threadIdx.x;    // 256
    const int z     = tid & 15;
    const int ylane = tid >> 4;     // 0..15

    #pragma unroll
    for (int i = 0; i < 27; i++) sm[i][tid] = 0.0f;
    __syncthreads();

    const float cr = com_r[bf * NZ + z];   // column center (real axis)
    const float ci = com_i[bf * NZ + z];   // row center (imag axis)

    const float dyv = (float)xi - ci;      // imag component (fixed per block)
    const float ayc = fmaxf(fabsf(dyv), 1e-30f);

    float* col0 = &sm[0][tid];
    const float* xrow = x + ((size_t)bf * NX + xi) * NY * NZ;

    float dxv = (float)ylane - cr;         // incremental: +16 per yo

    #pragma unroll 2
    for (int yo = 0; yo < NY / 16; yo++) {
        const float xv = xrow[yo * 256 + tid];    // fully coalesced

        // ---- custom atan2(dyv, dxv) ----
        float ax = fabsf(dxv);
        float mx = fmaxf(ax, ayc);
        float mn = fminf(ax, ayc);
        float t  = __fdividef(mn, mx);            // t in [0,1]
        float t2 = t * t;
        float p  = fmaf(t2, -0.0117212f, 0.05265332f);
        p = fmaf(t2, p, -0.11643287f);
        p = fmaf(t2, p,  0.19354346f);
        p = fmaf(t2, p, -0.33262347f);
        p = fmaf(t2, p,  0.99997726f);
        float a = t * p;
        if (ayc > ax)  a = 1.5707963267948966f - a;
        if (dxv < 0.f) a = 3.1415926535897932f - a;
        a = copysignf(a, dyv);                    // theta = atan2(dy, dx)

        // bin coordinate: u = (theta + pi) * 12/pi in (0, 24]
        const float uu  = fmaf(a, 3.8197186342054880f, 12.0f);
        const float r0f = rintf(uu);
        const float du  = uu - r0f;               // in [-0.5, 0.5]
        const int   r0  = (int)r0f;               // 0..24
        const float ts  = du * SC;

        // 3 nearest bins (k = -1..1): w_k = 2^(-(ts - k*SC)^2)
        const float dm = ts + SC;
        const float dp = ts - SC;
        float w0, wm1, w1;
        asm("ex2.approx.ftz.f32 %0, %1;" : "=f"(w0)  : "f"(-ts * ts));
        asm("ex2.approx.ftz.f32 %0, %1;" : "=f"(wm1) : "f"(-dm * dm));
        asm("ex2.approx.ftz.f32 %0, %1;" : "=f"(w1)  : "f"(-dp * dp));

        // rows r0 .. r0+2 (immediate smem offsets), row = bin + 1
        float* pacc = col0 + r0 * 256;
        pacc[0]   = fmaf(wm1, xv, pacc[0]);
        pacc[256] = fmaf(w0,  xv, pacc[256]);
        pacc[512] = fmaf(w1,  xv, pacc[512]);

        dxv += 16.0f;
    }

    __syncthreads();

    // ---- block reduction: fold 27 rows -> 24 bins, RED into global sums ----
    for (int p2 = tid; p2 < NR * NZ; p2 += 256) {
        const int zz = p2 & 15;
        const int rr = p2 >> 4;          // bin 0..23
        float s = 0.0f;
        #pragma unroll
        for (int j = 0; j < 16; j++) s += sm[rr + 1][zz + 16 * j];
        if (rr < 2) {                    // rows 25,26 = bins 24,25 wrap -> 0,1
            #pragma unroll
            for (int j = 0; j < 16; j++) s += sm[rr + 25][zz + 16 * j];
        }
        if (rr == 23) {                  // row 0 = bin -1 wraps -> 23
            #pragma unroll
            for (int j = 0; j < 16; j++) s += sm[0][zz + 16 * j];
        }
        atomicAdd(&g_sum[(bf * NR + rr) * NZ + zz], s);   // RED (result unused)
    }

    // ---- completion protocol: one gpu-scope fence per BLOCK, not per thread ----
    __syncthreads();                     // all REDs of this block happen-before tid0
    if (tid == 0) {
        __threadfence();                 // publish this block's REDs (gpu scope)
        int n = atomicAdd(&g_count[bf], 1);
        s_last = (n == NBLK - 1);
        if (s_last) __threadfence();     // acquire: make all blocks' REDs visible
    }
    __syncthreads();
    if (!s_last) return;

    // ---- last block per bf finalizes its 384 outputs ----
    for (int o = tid; o < NR * NZ; o += 256) {
        const int idx = bf * NR * NZ + o;
        float s = __ldcg(&g_sum[idx]);
        out[idx] = sqrtf(7.9788456080286535f * s);
        g_sum[idx] = 0.0f;               // reset for next graph replay
    }
    if (tid == 0) g_count[bf] = 0;
}

extern "C" void kernel_launch(void* const* d_in, const int* in_sizes, int n_in,
                              void* d_out, int out_size) {
    const float* x     = (const float*)d_in[0];
    const float* com_r = (const float*)d_in[1];
    const float* com_i = (const float*)d_in[2];
    float* out = (float*)d_out;

    dim3 grid(NBLK, NBF);
    gre_fused_kernel<<<grid, 256>>>(x, com_r, com_i, out);
}

// round 8
// speedup vs baseline: 1.0152x; 1.0152x over previous
#include <cuda_runtime.h>
#include <math.h>

// Problem shapes (fixed by setup_inputs)
#define NB 2
#define NF 2
#define NX 256
#define NY 256
#define NZ 16
#define NR 24
#define NBF (NB*NF)
#define NOUT (NBF*NR*NZ)   // 1536

#define NBLK NX            // 256 blocks per bf (1 x-row each)

// SC = sqrt(50*log2(e)) * (pi/12)  (bin spacing in ex2-scaled units)
#define SC   2.2235193f

// Global accumulators (zero-init; last block per bf resets them each launch)
__device__ float g_sum[NOUT];
__device__ int   g_count[NBF];

__global__ __launch_bounds__(256, 7)
void gre_fused_kernel(const float* __restrict__ x,
                      const float* __restrict__ com_r,
                      const float* __restrict__ com_i,
                      float* __restrict__ out) {
    __shared__ float sm[27][256];   // row i = bin (i-1); bins -1..25
    __shared__ bool  s_last;

    const int bf  = blockIdx.y;     // 0..3
    const int xi  = blockIdx.x;     // x-row 0..255
    const int tid = threadIdx.x;    // 256
    const int z     = tid & 15;
    const int ylane = tid >> 4;     // 0..15

    #pragma unroll
    for (int i = 0; i < 27; i++) sm[i][tid] = 0.0f;
    __syncthreads();

    const float cr = com_r[bf * NZ + z];   // column center (real axis)
    const float ci = com_i[bf * NZ + z];   // row center (imag axis)

    const float dyv = (float)xi - ci;      // imag component (fixed per block)
    const float ayc = fmaxf(fabsf(dyv), 1e-30f);

    float* col0 = &sm[0][tid];
    const float* xrow = x + ((size_t)bf * NX + xi) * NY * NZ;

    float dxv = (float)ylane - cr;         // incremental: +16 per yo

    #pragma unroll 2
    for (int yo = 0; yo < NY / 16; yo++) {
        const float xv = xrow[yo * 256 + tid];    // fully coalesced

        // ---- custom atan2(dyv, dxv) ----
        float ax = fabsf(dxv);
        float mx = fmaxf(ax, ayc);
        float mn = fminf(ax, ayc);
        float t  = __fdividef(mn, mx);            // t in [0,1]
        float t2 = t * t;
        float p  = fmaf(t2, -0.0117212f, 0.05265332f);
        p = fmaf(t2, p, -0.11643287f);
        p = fmaf(t2, p,  0.19354346f);
        p = fmaf(t2, p, -0.33262347f);
        p = fmaf(t2, p,  0.99997726f);
        float a = t * p;
        if (ayc > ax)  a = 1.5707963267948966f - a;
        if (dxv < 0.f) a = 3.1415926535897932f - a;
        a = copysignf(a, dyv);                    // theta = atan2(dy, dx)

        // bin coordinate: u = (theta + pi) * 12/pi in (0, 24]
        const float uu  = fmaf(a, 3.8197186342054880f, 12.0f);
        const float r0f = rintf(uu);
        const float du  = uu - r0f;               // in [-0.5, 0.5]
        const int   r0  = (int)r0f;               // 0..24
        const float ts  = du * SC;

        // 3 nearest bins (k = -1..1): w_k = 2^(-(ts - k*SC)^2)
        const float dm = ts + SC;
        const float dp = ts - SC;
        float w0, wm1, w1;
        asm("ex2.approx.ftz.f32 %0, %1;" : "=f"(w0)  : "f"(-ts * ts));
        asm("ex2.approx.ftz.f32 %0, %1;" : "=f"(wm1) : "f"(-dm * dm));
        asm("ex2.approx.ftz.f32 %0, %1;" : "=f"(w1)  : "f"(-dp * dp));

        // rows r0 .. r0+2 (immediate smem offsets), row = bin + 1
        float* pacc = col0 + r0 * 256;
        pacc[0]   = fmaf(wm1, xv, pacc[0]);
        pacc[256] = fmaf(w0,  xv, pacc[256]);
        pacc[512] = fmaf(w1,  xv, pacc[512]);

        dxv += 16.0f;
    }

    __syncthreads();

    // ---- block reduction: fold 27 rows -> 24 bins, RED into global sums ----
    for (int p2 = tid; p2 < NR * NZ; p2 += 256) {
        const int zz = p2 & 15;
        const int rr = p2 >> 4;          // bin 0..23
        float s = 0.0f;
        #pragma unroll
        for (int j = 0; j < 16; j++) s += sm[rr + 1][zz + 16 * j];
        if (rr < 2) {                    // rows 25,26 = bins 24,25 wrap -> 0,1
            #pragma unroll
            for (int j = 0; j < 16; j++) s += sm[rr + 25][zz + 16 * j];
        }
        if (rr == 23) {                  // row 0 = bin -1 wraps -> 23
            #pragma unroll
            for (int j = 0; j < 16; j++) s += sm[0][zz + 16 * j];
        }
        atomicAdd(&g_sum[(bf * NR + rr) * NZ + zz], s);   // RED (result unused)
    }

    // ---- completion protocol: one gpu-scope fence per BLOCK, not per thread ----
    __syncthreads();                     // all REDs of this block happen-before tid0
    if (tid == 0) {
        __threadfence();                 // publish this block's REDs (gpu scope)
        int n = atomicAdd(&g_count[bf], 1);
        s_last = (n == NBLK - 1);
        if (s_last) __threadfence();     // acquire: make all blocks' REDs visible
    }
    __syncthreads();
    if (!s_last) return;

    // ---- last block per bf finalizes its 384 outputs ----
    for (int o = tid; o < NR * NZ; o += 256) {
        const int idx = bf * NR * NZ + o;
        float s = __ldcg(&g_sum[idx]);
        out[idx] = sqrtf(7.9788456080286535f * s);
        g_sum[idx] = 0.0f;               // reset for next graph replay
    }
    if (tid == 0) g_count[bf] = 0;
}

extern "C" void kernel_launch(void* const* d_in, const int* in_sizes, int n_in,
                              void* d_out, int out_size) {
    const float* x     = (const float*)d_in[0];
    const float* com_r = (const float*)d_in[1];
    const float* com_i = (const float*)d_in[2];
    float* out = (float*)d_out;

    dim3 grid(NBLK, NBF);
    gre_fused_kernel<<<grid, 256>>>(x, com_r, com_i, out);
}

// round 9
// speedup vs baseline: 1.0348x; 1.0193x over previous
#include <cuda_runtime.h>
#include <math.h>

// Problem shapes (fixed by setup_inputs)
#define NB 2
#define NF 2
#define NX 256
#define NY 256
#define NZ 16
#define NR 24
#define NBF (NB*NF)
#define NOUT (NBF*NR*NZ)   // 1536

#define NBLK NX            // 256 blocks per bf (1 x-row each)

// SC = sqrt(50*log2(e)) * (pi/12)  (bin spacing in ex2-scaled units)
#define SC   2.2235193f

// Global accumulators (zero-init; last block per bf resets them each launch)
__device__ float g_sum[NOUT];
__device__ int   g_count[NBF];

__global__ __launch_bounds__(256, 7)
void gre_fused_kernel(const float* __restrict__ x,
                      const float* __restrict__ com_r,
                      const float* __restrict__ com_i,
                      float* __restrict__ out) {
    __shared__ float sm[27][256];   // row i = bin (i-1); bins -1..25
    __shared__ bool  s_last;

    const int bf  = blockIdx.y;     // 0..3
    const int xi  = blockIdx.x;     // x-row 0..255
    const int tid = threadIdx.x;    // 256
    const int z     = tid & 15;
    const int ylane = tid >> 4;     // 0..15

    #pragma unroll
    for (int i = 0; i < 27; i++) sm[i][tid] = 0.0f;
    __syncthreads();

    const float cr = com_r[bf * NZ + z];   // column center (real axis)
    const float ci = com_i[bf * NZ + z];   // row center (imag axis)

    const float dyv = (float)xi - ci;      // imag component (fixed per block)
    const float ayc = fmaxf(fabsf(dyv), 1e-30f);

    float* col0 = &sm[0][tid];
    const float* xrow = x + ((size_t)bf * NX + xi) * NY * NZ;

    float dxv = (float)ylane - cr;         // incremental: +16 per yo

    #pragma unroll 2
    for (int yo = 0; yo < NY / 16; yo++) {
        const float xv = xrow[yo * 256 + tid];    // fully coalesced

        // ---- custom atan2(dyv, dxv) ----
        float ax = fabsf(dxv);
        float mx = fmaxf(ax, ayc);
        float mn = fminf(ax, ayc);
        float t  = __fdividef(mn, mx);            // t in [0,1]
        float t2 = t * t;
        float p  = fmaf(t2, -0.0117212f, 0.05265332f);
        p = fmaf(t2, p, -0.11643287f);
        p = fmaf(t2, p,  0.19354346f);
        p = fmaf(t2, p, -0.33262347f);
        p = fmaf(t2, p,  0.99997726f);
        float a = t * p;
        if (ayc > ax)  a = 1.5707963267948966f - a;
        if (dxv < 0.f) a = 3.1415926535897932f - a;
        a = copysignf(a, dyv);                    // theta = atan2(dy, dx)

        // bin coordinate: u = (theta + pi) * 12/pi in (0, 24]
        const float uu  = fmaf(a, 3.8197186342054880f, 12.0f);
        const float r0f = rintf(uu);
        const float du  = uu - r0f;               // in [-0.5, 0.5]
        const int   r0  = (int)r0f;               // 0..24
        const float ts  = du * SC;

        // 3 nearest bins (k = -1..1): w_k = 2^(-(ts - k*SC)^2)
        const float dm = ts + SC;
        const float dp = ts - SC;
        float w0, wm1, w1;
        asm("ex2.approx.ftz.f32 %0, %1;" : "=f"(w0)  : "f"(-ts * ts));
        asm("ex2.approx.ftz.f32 %0, %1;" : "=f"(wm1) : "f"(-dm * dm));
        asm("ex2.approx.ftz.f32 %0, %1;" : "=f"(w1)  : "f"(-dp * dp));

        // rows r0 .. r0+2 (immediate smem offsets), row = bin + 1
        float* pacc = col0 + r0 * 256;
        pacc[0]   = fmaf(wm1, xv, pacc[0]);
        pacc[256] = fmaf(w0,  xv, pacc[256]);
        pacc[512] = fmaf(w1,  xv, pacc[512]);

        dxv += 16.0f;
    }

    __syncthreads();

    // ---- block reduction: fold 27 rows -> 24 bins, RED into global sums ----
    for (int p2 = tid; p2 < NR * NZ; p2 += 256) {
        const int zz = p2 & 15;
        const int rr = p2 >> 4;          // bin 0..23
        float s = 0.0f;
        #pragma unroll
        for (int j = 0; j < 16; j++) s += sm[rr + 1][zz + 16 * j];
        if (rr < 2) {                    // rows 25,26 = bins 24,25 wrap -> 0,1
            #pragma unroll
            for (int j = 0; j < 16; j++) s += sm[rr + 25][zz + 16 * j];
        }
        if (rr == 23) {                  // row 0 = bin -1 wraps -> 23
            #pragma unroll
            for (int j = 0; j < 16; j++) s += sm[0][zz + 16 * j];
        }
        atomicAdd(&g_sum[(bf * NR + rr) * NZ + zz], s);   // RED (result unused)
    }

    // ---- completion protocol: one gpu-scope fence per BLOCK, not per thread ----
    __syncthreads();                     // all REDs of this block happen-before tid0
    if (tid == 0) {
        __threadfence();                 // publish this block's REDs (gpu scope)
        int n = atomicAdd(&g_count[bf], 1);
        s_last = (n == NBLK - 1);
        if (s_last) __threadfence();     // acquire: make all blocks' REDs visible
    }
    __syncthreads();
    if (!s_last) return;

    // ---- last block per bf finalizes its 384 outputs ----
    for (int o = tid; o < NR * NZ; o += 256) {
        const int idx = bf * NR * NZ + o;
        float s = __ldcg(&g_sum[idx]);
        out[idx] = sqrtf(7.9788456080286535f * s);
        g_sum[idx] = 0.0f;               // reset for next graph replay
    }
    if (tid == 0) g_count[bf] = 0;
}

extern "C" void kernel_launch(void* const* d_in, const int* in_sizes, int n_in,
                              void* d_out, int out_size) {
    const float* x     = (const float*)d_in[0];
    const float* com_r = (const float*)d_in[1];
    const float* com_i = (const float*)d_in[2];
    float* out = (float*)d_out;

    dim3 grid(NBLK, NBF);
    gre_fused_kernel<<<grid, 256>>>(x, com_r, com_i, out);
}